// round 15
// baseline (speedup 1.0000x reference)
#include <cuda_runtime.h>
#include <cuda_fp16.h>
#include <cstdint>

#define BN 8192
#define CN 16
#define DN 256
#define RN 64
#define EN 32
#define ORDN 16
#define LN 32

#define MT 128   // bodies per CTA
#define NH 128   // j-half per CTA
#define KC 32    // K chunk (two k16 mma tiles)

// Scratch: 4 partials per (b,c): [b][c][nh*2 + ngroup]; all written each launch
__device__ float g_q4[BN * CN * 4];

// smem u32 layout (per CTA, 33280 B):
//  Dhi [0,2048)  Dlo [2048,4096)        8 KB each
//  Bhi [4096,6208)  Blo [6208,8320)     8448 B each (33-u32-pair padded rows)
#define SM_DLO 2048
#define SM_BHI 4096
#define SM_BLO 6208
#define SM_U32 8320

__device__ __forceinline__ uint32_t pk_h2(float a, float b) {
    __half2 h = __floats2half2_rn(a, b);  // .x = low half = first arg
    return *reinterpret_cast<uint32_t*>(&h);
}

// mma m16n8k16 fp16 -> fp32 accum (sm_80+ baseline; valid on plain sm_100)
__device__ __forceinline__ void mma_f16(float* c, uint4 a, uint2 b) {
    asm volatile(
        "mma.sync.aligned.m16n8k16.row.col.f32.f16.f16.f32 "
        "{%0,%1,%2,%3}, {%4,%5,%6,%7}, {%8,%9}, {%0,%1,%2,%3};"
        : "+f"(c[0]), "+f"(c[1]), "+f"(c[2]), "+f"(c[3])
        : "r"(a.x), "r"(a.y), "r"(a.z), "r"(a.w), "r"(b.x), "r"(b.y));
}

// ---------------------------------------------------------------------------
// quad_mma_kernel: q-partials of d2 over one j-half:
//   q[b,c,half,ng] = sum_{j in ng-quarter} ( sum_i sig[c,i,j]*(mu[c,i]-z[b,i]) )^2
// fp16x3 split (hh + hl + lh) on mma.sync m16n8k16.
// grid (BN/MT, 2, CN), 256 thr, 2 CTAs/SM. Warp tile M32 x N64.
// Register-prefetch pipeline: GMEM loads for chunk kt+1 issue before compute(kt)
// so their latency hides under the mma phase. B staged via row-pair u32 stores.
// ---------------------------------------------------------------------------
__global__ __launch_bounds__(256, 2) void quad_mma_kernel(
    const float* __restrict__ z, const float* __restrict__ mu,
    const float* __restrict__ sig) {
    extern __shared__ uint32_t smu[];
    const int btile = blockIdx.x, nh = blockIdx.y, c = blockIdx.z;
    const int b0 = btile * MT, j0 = nh * NH;
    const int tid = threadIdx.x, wid = tid >> 5, lane = tid & 31;
    const int ms = (wid & 3) * 2;   // base m16 slot (covers 32 body rows)
    const int ng = wid >> 2;        // n-group: ntiles 8*ng .. 8*ng+7

    float acc[2][8][4];
#pragma unroll
    for (int sub = 0; sub < 2; sub++)
#pragma unroll
        for (int nt = 0; nt < 8; nt++)
#pragma unroll
            for (int i = 0; i < 4; i++) acc[sub][nt][i] = 0.f;

    const float* sigc = sig + (size_t)c * DN * DN;
    uint32_t* BhiU = smu + SM_BHI;
    uint32_t* BloU = smu + SM_BLO;

    // -------- prefetch registers --------
    float4 zr[4];        // z rows for D staging (4 iters x float4)
    float4 br0[2], br1[2];  // sig row-pairs for B staging (2 iters x 2 rows)

    // prefetch chunk 0
#pragma unroll
    for (int it = 0; it < 4; it++) {
        int idx = tid + it * 256;
        int b = idx >> 3, i4 = idx & 7;
        zr[it] = *(const float4*)(z + (size_t)(b0 + b) * DN + i4 * 4);
    }
#pragma unroll
    for (int it = 0; it < 2; it++) {
        int idx = tid + it * 256;
        int p = idx >> 5, j4 = idx & 31;
        br0[it] = *(const float4*)(sigc + (size_t)(2 * p) * DN + j0 + j4 * 4);
        br1[it] = *(const float4*)(sigc + (size_t)(2 * p + 1) * DN + j0 + j4 * 4);
    }

    for (int kt = 0; kt < DN / KC; kt++) {
        const int i0 = kt * KC;

        // --- store D (A operand): d = mu - z, fp16 hi/lo, fragment order ---
#pragma unroll
        for (int it = 0; it < 4; it++) {
            int idx = tid + it * 256;
            int b = idx >> 3, i4 = idx & 7;
            float4 m4 = *(const float4*)(mu + c * DN + i0 + i4 * 4);  // warp-uniform, L1-hot
            float4 zv = zr[it];
            float v[4] = {m4.x - zv.x, m4.y - zv.y, m4.z - zv.z, m4.w - zv.w};
            __half h0 = __float2half_rn(v[0]), h1 = __float2half_rn(v[1]);
            __half h2 = __float2half_rn(v[2]), h3 = __float2half_rn(v[3]);
            float l0 = v[0] - __half2float(h0), l1 = v[1] - __half2float(h1);
            float l2 = v[2] - __half2float(h2), l3 = v[3] - __half2float(h3);
            int r = b & 15, g = r & 7, rh = r >> 3, mslot = b >> 4;
            int kt16 = i4 >> 2;
            int sl = (i4 >> 1) & 1;
            int t0 = (i4 & 1) * 2;
            int reg = rh + 2 * sl;
            int base = ((mslot * 2 + kt16) * 32 + g * 4 + t0) * 4 + reg;
            smu[base]              = pk_h2(__half2float(h0), __half2float(h1));
            smu[base + 4]          = pk_h2(__half2float(h2), __half2float(h3));
            smu[SM_DLO + base]     = pk_h2(l0, l1);
            smu[SM_DLO + base + 4] = pk_h2(l2, l3);
        }
        // --- store B: row-pair u32 packing (k-parity halves in one store) ---
#pragma unroll
        for (int it = 0; it < 2; it++) {
            int idx = tid + it * 256;          // 0..511
            int p = idx >> 5, j4 = idx & 31;   // row pair (2p, 2p+1), j float4
            int kt16 = p >> 3, t = p & 3, sl = (p >> 2) & 1;
            float v0[4] = {br0[it].x, br0[it].y, br0[it].z, br0[it].w};
            float v1[4] = {br1[it].x, br1[it].y, br1[it].z, br1[it].w};
#pragma unroll
            for (int e = 0; e < 4; e++) {
                int jl = j4 * 4 + e;
                int nt = jl >> 3, g = jl & 7;
                int ui = ((kt16 * 16 + nt) * 33 + g * 4 + t) * 2 + sl;
                __half h0 = __float2half_rn(v0[e]);
                __half h1 = __float2half_rn(v1[e]);
                BhiU[ui] = pk_h2(__half2float(h0), __half2float(h1));
                BloU[ui] = pk_h2(v0[e] - __half2float(h0), v1[e] - __half2float(h1));
            }
        }
        __syncthreads();

        // --- issue next chunk's GMEM loads (latency hides under compute) ---
        if (kt < DN / KC - 1) {
            const int i1 = i0 + KC;
#pragma unroll
            for (int it = 0; it < 4; it++) {
                int idx = tid + it * 256;
                int b = idx >> 3, i4 = idx & 7;
                zr[it] = *(const float4*)(z + (size_t)(b0 + b) * DN + i1 + i4 * 4);
            }
#pragma unroll
            for (int it = 0; it < 2; it++) {
                int idx = tid + it * 256;
                int p = idx >> 5, j4 = idx & 31;
                br0[it] = *(const float4*)(sigc + (size_t)(i1 + 2 * p) * DN + j0 + j4 * 4);
                br1[it] = *(const float4*)(sigc + (size_t)(i1 + 2 * p + 1) * DN + j0 + j4 * 4);
            }
        }

        // --- compute: 2 k16-tiles x (2 m-subs x 8 ntiles) x {hh, hl, lh} ---
        const uint4* Dhi4 = (const uint4*)smu;
        const uint4* Dlo4 = (const uint4*)(smu + SM_DLO);
        const uint2* Bhi2 = (const uint2*)BhiU;
        const uint2* Blo2 = (const uint2*)BloU;
#pragma unroll
        for (int ktile = 0; ktile < 2; ktile++) {
            uint4 ah0 = Dhi4[((ms + 0) * 2 + ktile) * 32 + lane];
            uint4 al0 = Dlo4[((ms + 0) * 2 + ktile) * 32 + lane];
            uint4 ah1 = Dhi4[((ms + 1) * 2 + ktile) * 32 + lane];
            uint4 al1 = Dlo4[((ms + 1) * 2 + ktile) * 32 + lane];
#pragma unroll
            for (int nt = 0; nt < 8; nt++) {
                const int ntg = ng * 8 + nt;
                uint2 bh = Bhi2[(ktile * 16 + ntg) * 33 + lane];
                uint2 bl = Blo2[(ktile * 16 + ntg) * 33 + lane];
                mma_f16(acc[0][nt], ah0, bh);
                mma_f16(acc[0][nt], ah0, bl);
                mma_f16(acc[0][nt], al0, bh);
                mma_f16(acc[1][nt], ah1, bh);
                mma_f16(acc[1][nt], ah1, bl);
                mma_f16(acc[1][nt], al1, bh);
            }
        }
        __syncthreads();  // all warps done reading smem before next store phase
    }

    // Epilogue: per m-sub, q = sum_j acc^2 over this warp's n-quarter.
#pragma unroll
    for (int sub = 0; sub < 2; sub++) {
        float q0 = 0.f, q1 = 0.f;
#pragma unroll
        for (int nt = 0; nt < 8; nt++) {
            q0 += acc[sub][nt][0] * acc[sub][nt][0] + acc[sub][nt][1] * acc[sub][nt][1];
            q1 += acc[sub][nt][2] * acc[sub][nt][2] + acc[sub][nt][3] * acc[sub][nt][3];
        }
        q0 += __shfl_xor_sync(0xffffffffu, q0, 1);
        q0 += __shfl_xor_sync(0xffffffffu, q0, 2);
        q1 += __shfl_xor_sync(0xffffffffu, q1, 1);
        q1 += __shfl_xor_sync(0xffffffffu, q1, 2);
        if ((lane & 3) == 0) {
            int b = b0 + (ms + sub) * 16 + (lane >> 2);
            g_q4[(((size_t)b * CN + c) * 2 + nh) * 2 + ng]       = q0;
            g_q4[(((size_t)(b + 8) * CN + c) * 2 + nh) * 2 + ng] = q1;
        }
    }
}

// ---------------------------------------------------------------------------
// Kernel B: d2 -> softmax -> ARX recursion -> weighted output.
// ---------------------------------------------------------------------------
__global__ __launch_bounds__(256) void arx_out_kernel(
    const float* __restrict__ y, const float* __restrict__ u,
    const float* __restrict__ a_coef, const float* __restrict__ b_coef,
    const float* __restrict__ bias, float* __restrict__ out) {
    __shared__ float ps[16 * 16 * 33];
    __shared__ float acs[CN * ORDN];
    __shared__ float bcs[CN * EN];
    __shared__ float bss[CN];

    const int tid = threadIdx.x;
    if (tid < CN * ORDN) acs[tid] = a_coef[tid];
    for (int i = tid; i < CN * EN; i += 256) bcs[i] = b_coef[i];
    if (tid < CN) bss[tid] = bias[tid];
    __syncthreads();

    const int tb = tid >> 4;
    const int tc = tid & 15;
    const int b  = blockIdx.x * 16 + tb;

    const float4 qv = *(const float4*)&g_q4[((size_t)b * CN + tc) * 4];
    float d2 = fmaxf((qv.x + qv.y) + (qv.z + qv.w), 1e-8f);

    float mn = d2;
#pragma unroll
    for (int m = 8; m; m >>= 1) mn = fminf(mn, __shfl_xor_sync(0xffffffffu, mn, m));
    float e = expf(-(d2 - mn));
    float ssum = e;
#pragma unroll
    for (int m = 8; m; m >>= 1) ssum += __shfl_xor_sync(0xffffffffu, ssum, m);
    float psi = e / ssum;

    const float4* uv = (const float4*)(u + ((size_t)b * CN + tc) * EN);
    float ub = bss[tc];
#pragma unroll
    for (int k = 0; k < EN / 4; k++) {
        float4 uu = uv[k];
        const float* bc = &bcs[tc * EN + k * 4];
        ub += uu.x * bc[0] + uu.y * bc[1] + uu.z * bc[2] + uu.w * bc[3];
    }

    float s[ORDN];
    const float4* yv = (const float4*)(y + ((size_t)b * CN + tc) * RN + (RN - ORDN));
#pragma unroll
    for (int k = 0; k < ORDN / 4; k++) {
        float4 t = yv[k];
        s[k * 4 + 0] = t.x; s[k * 4 + 1] = t.y;
        s[k * 4 + 2] = t.z; s[k * 4 + 3] = t.w;
    }
    float ar[ORDN];
#pragma unroll
    for (int o = 0; o < ORDN; o++) ar[o] = acs[tc * ORDN + o];

    float* myps = &ps[(tb * 16 + tc) * 33];
#pragma unroll
    for (int l = 0; l < LN; l++) {
        float y0 = 0.f, y1 = 0.f;
#pragma unroll
        for (int o = 0; o < ORDN; o += 2) {
            y0 += s[o] * ar[o];
            y1 += s[o + 1] * ar[o + 1];
        }
        float yn = ub + y0 + y1;
#pragma unroll
        for (int o = 0; o < ORDN - 1; o++) s[o] = s[o + 1];
        s[ORDN - 1] = yn;
        myps[l] = psi * yn;
    }
    __syncthreads();

    for (int o = tid; o < 16 * LN; o += 256) {
        int bb = o >> 5, l = o & 31;
        float acc = 0.f;
#pragma unroll
        for (int cc = 0; cc < CN; cc++) acc += ps[(bb * 16 + cc) * 33 + l];
        out[(size_t)(blockIdx.x * 16 + bb) * LN + l] = acc;
    }
}

// ---------------------------------------------------------------------------
extern "C" void kernel_launch(void* const* d_in, const int* in_sizes, int n_in,
                              void* d_out, int out_size) {
    const float* y      = (const float*)d_in[0];
    const float* z      = (const float*)d_in[1];
    const float* u      = (const float*)d_in[2];
    const float* mu     = (const float*)d_in[3];
    const float* sig    = (const float*)d_in[4];
    const float* a_coef = (const float*)d_in[5];
    const float* b_coef = (const float*)d_in[6];
    const float* bias   = (const float*)d_in[7];
    float* out = (float*)d_out;

    const int qsmem = SM_U32 * sizeof(uint32_t);  // 33280 B
    cudaFuncSetAttribute(quad_mma_kernel,
                         cudaFuncAttributeMaxDynamicSharedMemorySize, qsmem);

    quad_mma_kernel<<<dim3(BN / MT, 2, CN), 256, qsmem>>>(z, mu, sig);
    arx_out_kernel<<<BN / 16, 256>>>(y, u, a_coef, b_coef, bias, out);
}

// round 16
// speedup vs baseline: 1.0516x; 1.0516x over previous
#include <cuda_runtime.h>
#include <cuda_fp16.h>
#include <cstdint>

#define BN 8192
#define CN 16
#define DN 256
#define RN 64
#define EN 32
#define ORDN 16
#define LN 32

#define MT 128   // bodies per CTA
#define NH 128   // j-half per CTA
#define KC 32    // K chunk (two k16 mma tiles)

// B-fragment chunk: Bhi (2112 u32, padded rows of 33 uint2) + Blo = 4224 u32
#define BCH_U4 1056           // uint4 per B chunk (16896 B)

// smem u32 layout (per CTA, 50176 B):
//  Dhi [0,2048)  Dlo [2048,4096)
//  Bbuf0 [4096,8320)  Bbuf1 [8320,12544)   (each 4224 u32: Bhi | Blo)
#define SM_DLO 2048
#define SM_B0  4096
#define SM_B1  8320
#define SM_U32 12544

// Scratch (__device__ globals; every element written each launch)
__device__ float g_q4[BN * CN * 4];
__device__ uint4 g_Bf[32 * 8 * BCH_U4];   // [c*2+nh][chunk] B fragments, 4.3 MB

__device__ __forceinline__ uint32_t smem_u32(const void* p) {
    uint32_t a;
    asm("{ .reg .u64 t; cvta.to.shared.u64 t, %1; cvt.u32.u64 %0, t; }" : "=r"(a) : "l"(p));
    return a;
}
__device__ __forceinline__ void cp_async16(uint32_t dst_smem, const void* src) {
    asm volatile("cp.async.ca.shared.global [%0], [%1], 16;"
                 :: "r"(dst_smem), "l"(src) : "memory");
}
__device__ __forceinline__ uint32_t pk_h2(float a, float b) {
    __half2 h = __floats2half2_rn(a, b);  // .x = low half = first arg
    return *reinterpret_cast<uint32_t*>(&h);
}

// mma m16n8k16 fp16 -> fp32 accum (sm_80+ baseline; valid on plain sm_100)
__device__ __forceinline__ void mma_f16(float* c, uint4 a, uint2 b) {
    asm volatile(
        "mma.sync.aligned.m16n8k16.row.col.f32.f16.f16.f32 "
        "{%0,%1,%2,%3}, {%4,%5,%6,%7}, {%8,%9}, {%0,%1,%2,%3};"
        : "+f"(c[0]), "+f"(c[1]), "+f"(c[2]), "+f"(c[3])
        : "r"(a.x), "r"(a.y), "r"(a.z), "r"(a.w), "r"(b.x), "r"(b.y));
}

// ---------------------------------------------------------------------------
// bfrag_kernel: precompute B fragments (fp16 hi/lo split of sig, K-major,
// padded fragment layout) into g_Bf. grid (CN, 2, 8 chunks), 256 thr.
// Layout identical bit-for-bit to round-14 in-kernel staging.
// ---------------------------------------------------------------------------
__global__ void bfrag_kernel(const float* __restrict__ sig) {
    __shared__ uint32_t bs[4224];   // Bhi [0,2112) | Blo [2112,4224)
    const int c = blockIdx.x, nh = blockIdx.y, ch = blockIdx.z;
    const int j0 = nh * NH, i0 = ch * KC;
    const int tid = threadIdx.x;
    const float* sigc = sig + (size_t)c * DN * DN;
    __half* BhiH = (__half*)bs;
    __half* BloH = (__half*)(bs + 2112);

#pragma unroll
    for (int it = 0; it < 4; it++) {
        int idx = tid + it * 256;          // 0..1023
        int ii = idx >> 5, j4 = idx & 31;
        float4 av = *(const float4*)(sigc + (size_t)(i0 + ii) * DN + j0 + j4 * 4);
        float v[4] = {av.x, av.y, av.z, av.w};
        int kk = ii & 15, kt16 = ii >> 4;
        int t = (kk & 7) >> 1, sl = kk >> 3, hp = kk & 1;
#pragma unroll
        for (int e = 0; e < 4; e++) {
            int jl = j4 * 4 + e;
            int nt = jl >> 3, g = jl & 7;
            int hidx = ((((kt16 * 16 + nt) * 33 + g * 4 + t) * 2 + sl) * 2) + hp;
            __half h = __float2half_rn(v[e]);
            BhiH[hidx] = h;
            BloH[hidx] = __float2half_rn(v[e] - __half2float(h));
        }
    }
    __syncthreads();

    uint4* dst = g_Bf + ((size_t)(c * 2 + nh) * 8 + ch) * BCH_U4;
    const uint4* src = (const uint4*)bs;
    for (int i = tid; i < BCH_U4; i += 256) dst[i] = src[i];
}

// ---------------------------------------------------------------------------
// quad_mma_kernel: q-partials of d2 over one j-half:
//   q[b,c,half,ng] = sum_{j in ng-quarter} ( sum_i sig[c,i,j]*(mu[c,i]-z[b,i]) )^2
// fp16x3 split (hh + hl + lh) on mma.sync m16n8k16. Warp tile M32 x N64.
// grid (BN/MT, 2, CN), 256 thr, 2 CTAs/SM.
// B staged via double-buffered cp.async of precomputed fragments (overlapped
// with compute); D staged in-kernel (btile-dependent, mu-folded).
// ---------------------------------------------------------------------------
__global__ __launch_bounds__(256, 2) void quad_mma_kernel(
    const float* __restrict__ z, const float* __restrict__ mu,
    const float* __restrict__ sig) {
    extern __shared__ uint32_t smu[];
    const uint32_t sb = smem_u32(smu);
    const int btile = blockIdx.x, nh = blockIdx.y, c = blockIdx.z;
    const int b0 = btile * MT;
    const int tid = threadIdx.x, wid = tid >> 5, lane = tid & 31;
    const int ms = (wid & 3) * 2;   // base m16 slot (covers 32 body rows)
    const int ng = wid >> 2;        // n-group: ntiles 8*ng .. 8*ng+7

    float acc[2][8][4];
#pragma unroll
    for (int sub = 0; sub < 2; sub++)
#pragma unroll
        for (int nt = 0; nt < 8; nt++)
#pragma unroll
            for (int i = 0; i < 4; i++) acc[sub][nt][i] = 0.f;

    const uint4* bsrc_base = g_Bf + (size_t)(c * 2 + nh) * 8 * BCH_U4;

    // prologue: cp.async B chunk 0 -> buf0
    {
        const uint4* src = bsrc_base;
        uint32_t dst = sb + SM_B0 * 4;
        for (int i = tid; i < BCH_U4; i += 256) cp_async16(dst + i * 16, src + i);
        asm volatile("cp.async.commit_group;" ::: "memory");
    }

    for (int kt = 0; kt < DN / KC; kt++) {
        const int i0 = kt * KC;

        // --- stage D (A operand): d = mu - z, fp16 hi/lo, fragment order ---
#pragma unroll
        for (int it = 0; it < 4; it++) {
            int idx = tid + it * 256;
            int b = idx >> 3, i4 = idx & 7;
            float4 zv = *(const float4*)(z + (size_t)(b0 + b) * DN + i0 + i4 * 4);
            float4 m4 = *(const float4*)(mu + c * DN + i0 + i4 * 4);  // warp-uniform
            float v[4] = {m4.x - zv.x, m4.y - zv.y, m4.z - zv.z, m4.w - zv.w};
            __half h0 = __float2half_rn(v[0]), h1 = __float2half_rn(v[1]);
            __half h2 = __float2half_rn(v[2]), h3 = __float2half_rn(v[3]);
            float l0 = v[0] - __half2float(h0), l1 = v[1] - __half2float(h1);
            float l2 = v[2] - __half2float(h2), l3 = v[3] - __half2float(h3);
            int r = b & 15, g = r & 7, rh = r >> 3, mslot = b >> 4;
            int kt16 = i4 >> 2;
            int sl = (i4 >> 1) & 1;
            int t0 = (i4 & 1) * 2;
            int reg = rh + 2 * sl;
            int base = ((mslot * 2 + kt16) * 32 + g * 4 + t0) * 4 + reg;
            smu[base]              = pk_h2(__half2float(h0), __half2float(h1));
            smu[base + 4]          = pk_h2(__half2float(h2), __half2float(h3));
            smu[SM_DLO + base]     = pk_h2(l0, l1);
            smu[SM_DLO + base + 4] = pk_h2(l2, l3);
        }

        // --- issue cp.async for B chunk kt+1 into the other buffer ---
        if (kt < DN / KC - 1) {
            const uint4* src = bsrc_base + (size_t)(kt + 1) * BCH_U4;
            uint32_t dst = sb + (SM_B0 + ((kt + 1) & 1) * 4224) * 4;
            for (int i = tid; i < BCH_U4; i += 256) cp_async16(dst + i * 16, src + i);
            asm volatile("cp.async.commit_group;" ::: "memory");
            asm volatile("cp.async.wait_group 1;" ::: "memory");  // chunk kt done
        } else {
            asm volatile("cp.async.wait_group 0;" ::: "memory");
        }
        __syncthreads();

        // --- compute: 2 k16-tiles x (2 m-subs x 8 ntiles) x {hh, hl, lh} ---
        const uint4* Dhi4 = (const uint4*)smu;
        const uint4* Dlo4 = (const uint4*)(smu + SM_DLO);
        const uint2* Bhi2 = (const uint2*)(smu + SM_B0 + (kt & 1) * 4224);
        const uint2* Blo2 = Bhi2 + 1056;
#pragma unroll
        for (int ktile = 0; ktile < 2; ktile++) {
            uint4 ah0 = Dhi4[((ms + 0) * 2 + ktile) * 32 + lane];
            uint4 al0 = Dlo4[((ms + 0) * 2 + ktile) * 32 + lane];
            uint4 ah1 = Dhi4[((ms + 1) * 2 + ktile) * 32 + lane];
            uint4 al1 = Dlo4[((ms + 1) * 2 + ktile) * 32 + lane];
#pragma unroll
            for (int nt = 0; nt < 8; nt++) {
                const int ntg = ng * 8 + nt;
                uint2 bh = Bhi2[(ktile * 16 + ntg) * 33 + lane];
                uint2 bl = Blo2[(ktile * 16 + ntg) * 33 + lane];
                mma_f16(acc[0][nt], ah0, bh);
                mma_f16(acc[0][nt], ah0, bl);
                mma_f16(acc[0][nt], al0, bh);
                mma_f16(acc[1][nt], ah1, bh);
                mma_f16(acc[1][nt], ah1, bl);
                mma_f16(acc[1][nt], al1, bh);
            }
        }
        __syncthreads();  // all warps done with D + B(kt) before next stores
    }

    // Epilogue: per m-sub, q = sum_j acc^2 over this warp's n-quarter.
#pragma unroll
    for (int sub = 0; sub < 2; sub++) {
        float q0 = 0.f, q1 = 0.f;
#pragma unroll
        for (int nt = 0; nt < 8; nt++) {
            q0 += acc[sub][nt][0] * acc[sub][nt][0] + acc[sub][nt][1] * acc[sub][nt][1];
            q1 += acc[sub][nt][2] * acc[sub][nt][2] + acc[sub][nt][3] * acc[sub][nt][3];
        }
        q0 += __shfl_xor_sync(0xffffffffu, q0, 1);
        q0 += __shfl_xor_sync(0xffffffffu, q0, 2);
        q1 += __shfl_xor_sync(0xffffffffu, q1, 1);
        q1 += __shfl_xor_sync(0xffffffffu, q1, 2);
        if ((lane & 3) == 0) {
            int b = b0 + (ms + sub) * 16 + (lane >> 2);
            g_q4[(((size_t)b * CN + c) * 2 + nh) * 2 + ng]       = q0;
            g_q4[(((size_t)(b + 8) * CN + c) * 2 + nh) * 2 + ng] = q1;
        }
    }
}

// ---------------------------------------------------------------------------
// Kernel B: d2 -> softmax -> ARX recursion -> weighted output.
// ---------------------------------------------------------------------------
__global__ __launch_bounds__(256) void arx_out_kernel(
    const float* __restrict__ y, const float* __restrict__ u,
    const float* __restrict__ a_coef, const float* __restrict__ b_coef,
    const float* __restrict__ bias, float* __restrict__ out) {
    __shared__ float ps[16 * 16 * 33];
    __shared__ float acs[CN * ORDN];
    __shared__ float bcs[CN * EN];
    __shared__ float bss[CN];

    const int tid = threadIdx.x;
    if (tid < CN * ORDN) acs[tid] = a_coef[tid];
    for (int i = tid; i < CN * EN; i += 256) bcs[i] = b_coef[i];
    if (tid < CN) bss[tid] = bias[tid];
    __syncthreads();

    const int tb = tid >> 4;
    const int tc = tid & 15;
    const int b  = blockIdx.x * 16 + tb;

    const float4 qv = *(const float4*)&g_q4[((size_t)b * CN + tc) * 4];
    float d2 = fmaxf((qv.x + qv.y) + (qv.z + qv.w), 1e-8f);

    float mn = d2;
#pragma unroll
    for (int m = 8; m; m >>= 1) mn = fminf(mn, __shfl_xor_sync(0xffffffffu, mn, m));
    float e = expf(-(d2 - mn));
    float ssum = e;
#pragma unroll
    for (int m = 8; m; m >>= 1) ssum += __shfl_xor_sync(0xffffffffu, ssum, m);
    float psi = e / ssum;

    const float4* uv = (const float4*)(u + ((size_t)b * CN + tc) * EN);
    float ub = bss[tc];
#pragma unroll
    for (int k = 0; k < EN / 4; k++) {
        float4 uu = uv[k];
        const float* bc = &bcs[tc * EN + k * 4];
        ub += uu.x * bc[0] + uu.y * bc[1] + uu.z * bc[2] + uu.w * bc[3];
    }

    float s[ORDN];
    const float4* yv = (const float4*)(y + ((size_t)b * CN + tc) * RN + (RN - ORDN));
#pragma unroll
    for (int k = 0; k < ORDN / 4; k++) {
        float4 t = yv[k];
        s[k * 4 + 0] = t.x; s[k * 4 + 1] = t.y;
        s[k * 4 + 2] = t.z; s[k * 4 + 3] = t.w;
    }
    float ar[ORDN];
#pragma unroll
    for (int o = 0; o < ORDN; o++) ar[o] = acs[tc * ORDN + o];

    float* myps = &ps[(tb * 16 + tc) * 33];
#pragma unroll
    for (int l = 0; l < LN; l++) {
        float y0 = 0.f, y1 = 0.f;
#pragma unroll
        for (int o = 0; o < ORDN; o += 2) {
            y0 += s[o] * ar[o];
            y1 += s[o + 1] * ar[o + 1];
        }
        float yn = ub + y0 + y1;
#pragma unroll
        for (int o = 0; o < ORDN - 1; o++) s[o] = s[o + 1];
        s[ORDN - 1] = yn;
        myps[l] = psi * yn;
    }
    __syncthreads();

    for (int o = tid; o < 16 * LN; o += 256) {
        int bb = o >> 5, l = o & 31;
        float acc = 0.f;
#pragma unroll
        for (int cc = 0; cc < CN; cc++) acc += ps[(bb * 16 + cc) * 33 + l];
        out[(size_t)(blockIdx.x * 16 + bb) * LN + l] = acc;
    }
}

// ---------------------------------------------------------------------------
extern "C" void kernel_launch(void* const* d_in, const int* in_sizes, int n_in,
                              void* d_out, int out_size) {
    const float* y      = (const float*)d_in[0];
    const float* z      = (const float*)d_in[1];
    const float* u      = (const float*)d_in[2];
    const float* mu     = (const float*)d_in[3];
    const float* sig    = (const float*)d_in[4];
    const float* a_coef = (const float*)d_in[5];
    const float* b_coef = (const float*)d_in[6];
    const float* bias   = (const float*)d_in[7];
    float* out = (float*)d_out;

    const int qsmem = SM_U32 * sizeof(uint32_t);  // 50176 B
    cudaFuncSetAttribute(quad_mma_kernel,
                         cudaFuncAttributeMaxDynamicSharedMemorySize, qsmem);

    bfrag_kernel<<<dim3(CN, 2, 8), 256>>>(sig);
    quad_mma_kernel<<<dim3(BN / MT, 2, CN), 256, qsmem>>>(z, mu, sig);
    arx_out_kernel<<<BN / 16, 256>>>(y, u, a_coef, b_coef, bias, out);
}

// round 17
// speedup vs baseline: 1.1003x; 1.0463x over previous
#include <cuda_runtime.h>
#include <cuda_fp16.h>
#include <cstdint>

#define BN 8192
#define CN 16
#define DN 256
#define RN 64
#define EN 32
#define ORDN 16
#define LN 32

#define MT 128   // bodies per CTA
#define NH 128   // j-half per CTA
#define KC 32    // K chunk (two k16 mma tiles)

#define BCH_U4 1056           // uint4 per B chunk (Bhi 2112 u32 + Blo 2112 u32)

// smem u32 layout (per CTA, 66560 B):
//  D0 [0,4096)  D1 [4096,8192)          (each: Dhi 2048 | Dlo 2048)
//  B0 [8192,12416)  B1 [12416,16640)    (each: Bhi 2112 | Blo 2112)
#define SM_D1  4096
#define SM_B0  8192
#define SM_B1  12416
#define SM_U32 16640

// Scratch (__device__ globals; every element written each launch)
__device__ float g_q4[BN * CN * 4];
__device__ uint4 g_Bf[32 * 8 * BCH_U4];   // [c*2+nh][chunk] B fragments, 4.3 MB

__device__ __forceinline__ uint32_t smem_u32(const void* p) {
    uint32_t a;
    asm("{ .reg .u64 t; cvta.to.shared.u64 t, %1; cvt.u32.u64 %0, t; }" : "=r"(a) : "l"(p));
    return a;
}
__device__ __forceinline__ void cp_async16(uint32_t dst_smem, const void* src) {
    asm volatile("cp.async.ca.shared.global [%0], [%1], 16;"
                 :: "r"(dst_smem), "l"(src) : "memory");
}
__device__ __forceinline__ uint32_t pk_h2(float a, float b) {
    __half2 h = __floats2half2_rn(a, b);  // .x = low half = first arg
    return *reinterpret_cast<uint32_t*>(&h);
}

// mma m16n8k16 fp16 -> fp32 accum (sm_80+ baseline; valid on plain sm_100)
__device__ __forceinline__ void mma_f16(float* c, uint4 a, uint2 b) {
    asm volatile(
        "mma.sync.aligned.m16n8k16.row.col.f32.f16.f16.f32 "
        "{%0,%1,%2,%3}, {%4,%5,%6,%7}, {%8,%9}, {%0,%1,%2,%3};"
        : "+f"(c[0]), "+f"(c[1]), "+f"(c[2]), "+f"(c[3])
        : "r"(a.x), "r"(a.y), "r"(a.z), "r"(a.w), "r"(b.x), "r"(b.y));
}

// ---------------------------------------------------------------------------
// bfrag_kernel: precompute B fragments (fp16 hi/lo split of sig, K-major,
// padded fragment layout) into g_Bf. grid (CN, 2, 8 chunks), 256 thr.
// ---------------------------------------------------------------------------
__global__ void bfrag_kernel(const float* __restrict__ sig) {
    __shared__ uint32_t bs[4224];   // Bhi [0,2112) | Blo [2112,4224)
    const int c = blockIdx.x, nh = blockIdx.y, ch = blockIdx.z;
    const int j0 = nh * NH, i0 = ch * KC;
    const int tid = threadIdx.x;
    const float* sigc = sig + (size_t)c * DN * DN;
    __half* BhiH = (__half*)bs;
    __half* BloH = (__half*)(bs + 2112);

#pragma unroll
    for (int it = 0; it < 4; it++) {
        int idx = tid + it * 256;          // 0..1023
        int ii = idx >> 5, j4 = idx & 31;
        float4 av = *(const float4*)(sigc + (size_t)(i0 + ii) * DN + j0 + j4 * 4);
        float v[4] = {av.x, av.y, av.z, av.w};
        int kk = ii & 15, kt16 = ii >> 4;
        int t = (kk & 7) >> 1, sl = kk >> 3, hp = kk & 1;
#pragma unroll
        for (int e = 0; e < 4; e++) {
            int jl = j4 * 4 + e;
            int nt = jl >> 3, g = jl & 7;
            int hidx = ((((kt16 * 16 + nt) * 33 + g * 4 + t) * 2 + sl) * 2) + hp;
            __half h = __float2half_rn(v[e]);
            BhiH[hidx] = h;
            BloH[hidx] = __float2half_rn(v[e] - __half2float(h));
        }
    }
    __syncthreads();

    uint4* dst = g_Bf + ((size_t)(c * 2 + nh) * 8 + ch) * BCH_U4;
    const uint4* src = (const uint4*)bs;
    for (int i = tid; i < BCH_U4; i += 256) dst[i] = src[i];
}

// ---------------------------------------------------------------------------
// D staging helper: fp16 hi/lo split of (mu - z) into fragment order.
// ---------------------------------------------------------------------------
__device__ __forceinline__ void store_D(uint32_t* dbuf, int tid, int it,
                                        float4 zv, float4 m4) {
    int idx = tid + it * 256;
    int b = idx >> 3, i4 = idx & 7;
    float v[4] = {m4.x - zv.x, m4.y - zv.y, m4.z - zv.z, m4.w - zv.w};
    __half h0 = __float2half_rn(v[0]), h1 = __float2half_rn(v[1]);
    __half h2 = __float2half_rn(v[2]), h3 = __float2half_rn(v[3]);
    float l0 = v[0] - __half2float(h0), l1 = v[1] - __half2float(h1);
    float l2 = v[2] - __half2float(h2), l3 = v[3] - __half2float(h3);
    int r = b & 15, g = r & 7, rh = r >> 3, mslot = b >> 4;
    int kt16 = i4 >> 2;
    int sl = (i4 >> 1) & 1;
    int t0 = (i4 & 1) * 2;
    int reg = rh + 2 * sl;
    int base = ((mslot * 2 + kt16) * 32 + g * 4 + t0) * 4 + reg;
    dbuf[base]             = pk_h2(__half2float(h0), __half2float(h1));
    dbuf[base + 4]         = pk_h2(__half2float(h2), __half2float(h3));
    dbuf[2048 + base]      = pk_h2(l0, l1);
    dbuf[2048 + base + 4]  = pk_h2(l2, l3);
}

// ---------------------------------------------------------------------------
// quad_mma_kernel: q-partials of d2 over one j-half (fp16x3 split GEMM).
// grid (BN/MT, 2, CN), 256 thr, 2 CTAs/SM. Warp tile M32 x N64.
// Fully double-buffered pipeline, ONE sync per chunk:
//   wait B(kt); sync; [LDG z(kt+1); cp.async B(kt+1)]; compute(kt); [STS D(kt+1)]
// ---------------------------------------------------------------------------
__global__ __launch_bounds__(256, 2) void quad_mma_kernel(
    const float* __restrict__ z, const float* __restrict__ mu,
    const float* __restrict__ sig) {
    extern __shared__ uint32_t smu[];
    const uint32_t sb = smem_u32(smu);
    const int btile = blockIdx.x, nh = blockIdx.y, c = blockIdx.z;
    const int b0 = btile * MT;
    const int tid = threadIdx.x, wid = tid >> 5, lane = tid & 31;
    const int ms = (wid & 3) * 2;   // base m16 slot (covers 32 body rows)
    const int ng = wid >> 2;        // n-group: ntiles 8*ng .. 8*ng+7

    float acc[2][8][4];
#pragma unroll
    for (int sub = 0; sub < 2; sub++)
#pragma unroll
        for (int nt = 0; nt < 8; nt++)
#pragma unroll
            for (int i = 0; i < 4; i++) acc[sub][nt][i] = 0.f;

    const uint4* bsrc_base = g_Bf + (size_t)(c * 2 + nh) * 8 * BCH_U4;

    // ---- prologue: stage D(0) into D0, cp.async B(0) into B0 ----
#pragma unroll
    for (int it = 0; it < 4; it++) {
        int idx = tid + it * 256;
        int b = idx >> 3, i4 = idx & 7;
        float4 zv = *(const float4*)(z + (size_t)(b0 + b) * DN + i4 * 4);
        float4 m4 = *(const float4*)(mu + c * DN + i4 * 4);
        store_D(smu, tid, it, zv, m4);
    }
    {
        uint32_t dst = sb + SM_B0 * 4;
        for (int i = tid; i < BCH_U4; i += 256) cp_async16(dst + i * 16, bsrc_base + i);
        asm volatile("cp.async.commit_group;" ::: "memory");
    }

    float4 zr[4];
    for (int kt = 0; kt < DN / KC; kt++) {
        asm volatile("cp.async.wait_group 0;" ::: "memory");  // B(kt) arrived
        __syncthreads();  // D(kt) stores + buffer reuse ordering

        const bool pre = (kt < DN / KC - 1);
        if (pre) {
            const int i1 = (kt + 1) * KC;
            // z LDGs issue now; latency hides under compute(kt)
#pragma unroll
            for (int it = 0; it < 4; it++) {
                int idx = tid + it * 256;
                int b = idx >> 3, i4 = idx & 7;
                zr[it] = *(const float4*)(z + (size_t)(b0 + b) * DN + i1 + i4 * 4);
            }
            const uint4* src = bsrc_base + (size_t)(kt + 1) * BCH_U4;
            uint32_t dst = sb + (SM_B0 + ((kt + 1) & 1) * 4224) * 4;
            for (int i = tid; i < BCH_U4; i += 256) cp_async16(dst + i * 16, src + i);
            asm volatile("cp.async.commit_group;" ::: "memory");
        }

        // --- compute(kt): 2 k16-tiles x (2 m-subs x 8 ntiles) x {hh, hl, lh} ---
        const uint4* Dhi4 = (const uint4*)(smu + (kt & 1) * SM_D1);
        const uint4* Dlo4 = Dhi4 + 512;
        const uint2* Bhi2 = (const uint2*)(smu + SM_B0 + (kt & 1) * 4224);
        const uint2* Blo2 = Bhi2 + 1056;
#pragma unroll
        for (int ktile = 0; ktile < 2; ktile++) {
            uint4 ah0 = Dhi4[((ms + 0) * 2 + ktile) * 32 + lane];
            uint4 al0 = Dlo4[((ms + 0) * 2 + ktile) * 32 + lane];
            uint4 ah1 = Dhi4[((ms + 1) * 2 + ktile) * 32 + lane];
            uint4 al1 = Dlo4[((ms + 1) * 2 + ktile) * 32 + lane];
#pragma unroll
            for (int nt = 0; nt < 8; nt++) {
                const int ntg = ng * 8 + nt;
                uint2 bh = Bhi2[(ktile * 16 + ntg) * 33 + lane];
                uint2 bl = Blo2[(ktile * 16 + ntg) * 33 + lane];
                mma_f16(acc[0][nt], ah0, bh);
                mma_f16(acc[0][nt], ah0, bl);
                mma_f16(acc[0][nt], al0, bh);
                mma_f16(acc[1][nt], ah1, bh);
                mma_f16(acc[1][nt], ah1, bl);
                mma_f16(acc[1][nt], al1, bh);
            }
        }

        // --- post-compute: cvt + STS of D(kt+1) into the other D buffer ---
        if (pre) {
            const int i1 = (kt + 1) * KC;
            uint32_t* dbuf = smu + ((kt + 1) & 1) * SM_D1;
#pragma unroll
            for (int it = 0; it < 4; it++) {
                int idx = tid + it * 256;
                int i4 = idx & 7;
                float4 m4 = *(const float4*)(mu + c * DN + i1 + i4 * 4);  // L1-hot
                store_D(dbuf, tid, it, zr[it], m4);
            }
        }
    }

    // Epilogue: per m-sub, q = sum_j acc^2 over this warp's n-quarter.
#pragma unroll
    for (int sub = 0; sub < 2; sub++) {
        float q0 = 0.f, q1 = 0.f;
#pragma unroll
        for (int nt = 0; nt < 8; nt++) {
            q0 += acc[sub][nt][0] * acc[sub][nt][0] + acc[sub][nt][1] * acc[sub][nt][1];
            q1 += acc[sub][nt][2] * acc[sub][nt][2] + acc[sub][nt][3] * acc[sub][nt][3];
        }
        q0 += __shfl_xor_sync(0xffffffffu, q0, 1);
        q0 += __shfl_xor_sync(0xffffffffu, q0, 2);
        q1 += __shfl_xor_sync(0xffffffffu, q1, 1);
        q1 += __shfl_xor_sync(0xffffffffu, q1, 2);
        if ((lane & 3) == 0) {
            int b = b0 + (ms + sub) * 16 + (lane >> 2);
            g_q4[(((size_t)b * CN + c) * 2 + nh) * 2 + ng]       = q0;
            g_q4[(((size_t)(b + 8) * CN + c) * 2 + nh) * 2 + ng] = q1;
        }
    }
}

// ---------------------------------------------------------------------------
// Kernel B: d2 -> softmax -> ARX recursion -> weighted output.
// ---------------------------------------------------------------------------
__global__ __launch_bounds__(256) void arx_out_kernel(
    const float* __restrict__ y, const float* __restrict__ u,
    const float* __restrict__ a_coef, const float* __restrict__ b_coef,
    const float* __restrict__ bias, float* __restrict__ out) {
    __shared__ float ps[16 * 16 * 33];
    __shared__ float acs[CN * ORDN];
    __shared__ float bcs[CN * EN];
    __shared__ float bss[CN];

    const int tid = threadIdx.x;
    if (tid < CN * ORDN) acs[tid] = a_coef[tid];
    for (int i = tid; i < CN * EN; i += 256) bcs[i] = b_coef[i];
    if (tid < CN) bss[tid] = bias[tid];
    __syncthreads();

    const int tb = tid >> 4;
    const int tc = tid & 15;
    const int b  = blockIdx.x * 16 + tb;

    const float4 qv = *(const float4*)&g_q4[((size_t)b * CN + tc) * 4];
    float d2 = fmaxf((qv.x + qv.y) + (qv.z + qv.w), 1e-8f);

    float mn = d2;
#pragma unroll
    for (int m = 8; m; m >>= 1) mn = fminf(mn, __shfl_xor_sync(0xffffffffu, mn, m));
    float e = expf(-(d2 - mn));
    float ssum = e;
#pragma unroll
    for (int m = 8; m; m >>= 1) ssum += __shfl_xor_sync(0xffffffffu, ssum, m);
    float psi = e / ssum;

    const float4* uv = (const float4*)(u + ((size_t)b * CN + tc) * EN);
    float ub = bss[tc];
#pragma unroll
    for (int k = 0; k < EN / 4; k++) {
        float4 uu = uv[k];
        const float* bc = &bcs[tc * EN + k * 4];
        ub += uu.x * bc[0] + uu.y * bc[1] + uu.z * bc[2] + uu.w * bc[3];
    }

    float s[ORDN];
    const float4* yv = (const float4*)(y + ((size_t)b * CN + tc) * RN + (RN - ORDN));
#pragma unroll
    for (int k = 0; k < ORDN / 4; k++) {
        float4 t = yv[k];
        s[k * 4 + 0] = t.x; s[k * 4 + 1] = t.y;
        s[k * 4 + 2] = t.z; s[k * 4 + 3] = t.w;
    }
    float ar[ORDN];
#pragma unroll
    for (int o = 0; o < ORDN; o++) ar[o] = acs[tc * ORDN + o];

    float* myps = &ps[(tb * 16 + tc) * 33];
#pragma unroll
    for (int l = 0; l < LN; l++) {
        float y0 = 0.f, y1 = 0.f;
#pragma unroll
        for (int o = 0; o < ORDN; o += 2) {
            y0 += s[o] * ar[o];
            y1 += s[o + 1] * ar[o + 1];
        }
        float yn = ub + y0 + y1;
#pragma unroll
        for (int o = 0; o < ORDN - 1; o++) s[o] = s[o + 1];
        s[ORDN - 1] = yn;
        myps[l] = psi * yn;
    }
    __syncthreads();

    for (int o = tid; o < 16 * LN; o += 256) {
        int bb = o >> 5, l = o & 31;
        float acc = 0.f;
#pragma unroll
        for (int cc = 0; cc < CN; cc++) acc += ps[(bb * 16 + cc) * 33 + l];
        out[(size_t)(blockIdx.x * 16 + bb) * LN + l] = acc;
    }
}

// ---------------------------------------------------------------------------
extern "C" void kernel_launch(void* const* d_in, const int* in_sizes, int n_in,
                              void* d_out, int out_size) {
    const float* y      = (const float*)d_in[0];
    const float* z      = (const float*)d_in[1];
    const float* u      = (const float*)d_in[2];
    const float* mu     = (const float*)d_in[3];
    const float* sig    = (const float*)d_in[4];
    const float* a_coef = (const float*)d_in[5];
    const float* b_coef = (const float*)d_in[6];
    const float* bias   = (const float*)d_in[7];
    float* out = (float*)d_out;

    const int qsmem = SM_U32 * sizeof(uint32_t);  // 66560 B
    cudaFuncSetAttribute(quad_mma_kernel,
                         cudaFuncAttributeMaxDynamicSharedMemorySize, qsmem);

    bfrag_kernel<<<dim3(CN, 2, 8), 256>>>(sig);
    quad_mma_kernel<<<dim3(BN / MT, 2, CN), 256, qsmem>>>(z, mu, sig);
    arx_out_kernel<<<BN / 16, 256>>>(y, u, a_coef, b_coef, bias, out);
}